// round 3
// baseline (speedup 1.0000x reference)
#include <cuda_runtime.h>
#include <cstdint>

// ---------------------------------------------------------------------------
// Grouped MoE MLP: per-expert  out = W2 @ swiglu(W1 @ x + b1) + b2
// fp32 I/O, TF32 mma.sync tensor-core path, fp32 accumulate.
//
// Tiling: BM=128, BN=128, BK=32, 256 threads (8 warps in 2x4), warp tile 64x32,
// mma.sync.aligned.m16n8k8.row.col.f32.tf32.tf32.f32, cp.async double buffer.
// Smem rows padded to LDT=36 floats -> frag LDS bank = (4r+c)%32, conflict-free.
// ---------------------------------------------------------------------------

#define BM 128
#define BN 128
#define BK 32
#define LDT 36
#define STAGE_FLOATS (BM * LDT)              // 4608 floats per tile stage
#define SMEM_FLOATS  (4 * STAGE_FLOATS)      // A x2 stages + B x2 stages
#define SMEM_BYTES   (SMEM_FLOATS * 4)       // 73728 bytes

#define ALPHA_SWIGLU 1.702f
#define LIMIT_SWIGLU 7.0f

// intermediate activations h = swiglu(gemm1) : [N, H] fp32 (16384 x 2880)
__device__ float g_h[16384ull * 2880ull];

// -------------------------- small PTX helpers ------------------------------

__device__ __forceinline__ void cp_async16(uint32_t saddr, const void* gptr, int src_bytes) {
    asm volatile("cp.async.cg.shared.global [%0], [%1], 16, %2;\n"
                 :: "r"(saddr), "l"(gptr), "r"(src_bytes));
}
__device__ __forceinline__ void cp_commit() {
    asm volatile("cp.async.commit_group;\n" ::);
}
template <int Npend>
__device__ __forceinline__ void cp_wait() {
    asm volatile("cp.async.wait_group %0;\n" :: "n"(Npend));
}
__device__ __forceinline__ uint32_t f2tf(float x) {
    uint32_t u;
    asm("cvt.rna.tf32.f32 %0, %1;" : "=r"(u) : "f"(x));
    return u;
}
__device__ __forceinline__ void mma_tf32(float* c, const uint32_t* a, const uint32_t* b) {
    asm volatile(
        "mma.sync.aligned.m16n8k8.row.col.f32.tf32.tf32.f32 "
        "{%0,%1,%2,%3}, {%4,%5,%6,%7}, {%8,%9}, {%0,%1,%2,%3};\n"
        : "+f"(c[0]), "+f"(c[1]), "+f"(c[2]), "+f"(c[3])
        : "r"(a[0]), "r"(a[1]), "r"(a[2]), "r"(a[3]), "r"(b[0]), "r"(b[1]));
}
__device__ __forceinline__ float swiglu_pair(float glu_in, float lin_in) {
    float g = fminf(glu_in, LIMIT_SWIGLU);
    float l = fminf(fmaxf(lin_in, -LIMIT_SWIGLU), LIMIT_SWIGLU);
    float sig = 1.0f / (1.0f + expf(-ALPHA_SWIGLU * g));
    return g * sig * (l + 1.0f);
}

// ---------------------------------------------------------------------------
// EPI = 0 : GEMM1 epilogue -> h[token, col/2] = swiglu(c_even+b_even, c_odd+b_odd)
// EPI = 1 : GEMM2 epilogue -> out[token, col] = c + bias
//
// A  : [rows_total, K] row-major (row stride = K). For EPI0: x. For EPI1: g_h.
// Bw : [E, Ncols, K]  (K contiguous) — matches mlp{1,2}_weight layout.
// bias: [E, Ncols]
// ---------------------------------------------------------------------------
template <int EPI>
__global__ void __launch_bounds__(256, 2)
grouped_gemm_tf32(const float* __restrict__ A,
                  const float* __restrict__ Bw,
                  const float* __restrict__ bias,
                  const int*   __restrict__ ntpe,
                  float*       __restrict__ Cout,
                  int K, int Ncols, int E, int mtiles_per_e, int Ntok) {
    // ---- resolve expert / m-tile from blockIdx.y ----
    int y  = blockIdx.y;
    int e  = y / mtiles_per_e;
    int mt = y - e * mtiles_per_e;

    int row0 = 0;
    #pragma unroll 1
    for (int i = 0; i < e; i++) row0 += ntpe[i];
    if (row0 >= Ntok) return;
    int rows = ntpe[e];
    if (rows > Ntok - row0) rows = Ntok - row0;
    if (mt * BM >= rows) return;

    int mrows     = rows - mt * BM;            // valid rows in this tile
    if (mrows > BM) mrows = BM;
    int row_start = row0 + mt * BM;
    int nbase     = blockIdx.x * BN;

    const float* gA = A  + (size_t)row_start * K;
    const float* gB = Bw + (size_t)e * Ncols * K + (size_t)nbase * K;

    extern __shared__ __align__(16) float smem[];
    float* As = smem;                          // [2][STAGE_FLOATS]
    float* Bs = smem + 2 * STAGE_FLOATS;       // [2][STAGE_FLOATS]

    int tid = threadIdx.x;

    // per-thread cp.async coords: 1024 float4 per tile, 4 per thread
    int lrow[4], lkv[4];
    #pragma unroll
    for (int l = 0; l < 4; l++) {
        int lin = tid + l * 256;
        lrow[l] = lin >> 3;
        lkv[l]  = (lin & 7) * 4;
    }

    int KT = K / BK;   // 90 for K = 2880

    auto load_tiles = [&](int kt, int buf) {
        const float* gAk = gA + kt * BK;
        const float* gBk = gB + kt * BK;
        float* sA = As + buf * STAGE_FLOATS;
        float* sB = Bs + buf * STAGE_FLOATS;
        #pragma unroll
        for (int l = 0; l < 4; l++) {
            int row = lrow[l], kv = lkv[l];
            // A
            bool va = (row < mrows);
            int  ra = va ? row : 0;
            uint32_t da = (uint32_t)__cvta_generic_to_shared(sA + row * LDT + kv);
            cp_async16(da, gAk + (size_t)ra * K + kv, va ? 16 : 0);
            // B
            bool vb = (nbase + row < Ncols);
            int  rb = vb ? row : 0;
            uint32_t db = (uint32_t)__cvta_generic_to_shared(sB + row * LDT + kv);
            cp_async16(db, gBk + (size_t)rb * K + kv, vb ? 16 : 0);
        }
        cp_commit();
    };

    // warp layout: 2 (M) x 4 (N); warp tile 64x32; 4x4 m16n8 mma tiles
    int wid  = tid >> 5;
    int lane = tid & 31;
    int wm   = wid & 1;
    int wn   = wid >> 1;
    int grp  = lane >> 2;        // 0..7
    int tig  = lane & 3;         // 0..3

    float acc[4][4][4];
    #pragma unroll
    for (int i = 0; i < 4; i++)
        #pragma unroll
        for (int j = 0; j < 4; j++)
            #pragma unroll
            for (int r = 0; r < 4; r++) acc[i][j][r] = 0.0f;

    load_tiles(0, 0);

    for (int kt = 0; kt < KT; kt++) {
        if (kt + 1 < KT) load_tiles(kt + 1, (kt + 1) & 1);
        else             cp_commit();          // empty group keeps count consistent
        cp_wait<1>();
        __syncthreads();

        const float* sA = As + (kt & 1) * STAGE_FLOATS;
        const float* sB = Bs + (kt & 1) * STAGE_FLOATS;

        #pragma unroll
        for (int s = 0; s < 4; s++) {
            int kb = s * 8;
            uint32_t afr[4][4];
            uint32_t bfr[4][2];
            #pragma unroll
            for (int i = 0; i < 4; i++) {
                const float* p = sA + (wm * 64 + i * 16 + grp) * LDT + kb + tig;
                afr[i][0] = f2tf(p[0]);
                afr[i][1] = f2tf(p[8 * LDT]);
                afr[i][2] = f2tf(p[4]);
                afr[i][3] = f2tf(p[8 * LDT + 4]);
            }
            #pragma unroll
            for (int j = 0; j < 4; j++) {
                const float* p = sB + (wn * 32 + j * 8 + grp) * LDT + kb + tig;
                bfr[j][0] = f2tf(p[0]);
                bfr[j][1] = f2tf(p[4]);
            }
            #pragma unroll
            for (int i = 0; i < 4; i++)
                #pragma unroll
                for (int j = 0; j < 4; j++)
                    mma_tf32(acc[i][j], afr[i], bfr[j]);
        }
        __syncthreads();
    }

    // ---- epilogue ----
    if (EPI == 0) {
        // bias + swiglu, write h[token, col/2]
        int Hout = Ncols >> 1;
        #pragma unroll
        for (int j = 0; j < 4; j++) {
            int col = nbase + wn * 32 + j * 8 + tig * 2;   // even
            float2 bb = *(const float2*)(bias + (size_t)e * Ncols + col);
            int hc = col >> 1;
            #pragma unroll
            for (int i = 0; i < 4; i++) {
                int m0 = wm * 64 + i * 16 + grp;
                if (m0 < mrows) {
                    float v = swiglu_pair(acc[i][j][0] + bb.x, acc[i][j][1] + bb.y);
                    Cout[(size_t)(row_start + m0) * Hout + hc] = v;
                }
                if (m0 + 8 < mrows) {
                    float v = swiglu_pair(acc[i][j][2] + bb.x, acc[i][j][3] + bb.y);
                    Cout[(size_t)(row_start + m0 + 8) * Hout + hc] = v;
                }
            }
        }
    } else {
        // bias add, write out[token, col..col+1]
        #pragma unroll
        for (int j = 0; j < 4; j++) {
            int col = nbase + wn * 32 + j * 8 + tig * 2;   // even
            if (col < Ncols) {
                float2 bb = *(const float2*)(bias + (size_t)e * Ncols + col);
                #pragma unroll
                for (int i = 0; i < 4; i++) {
                    int m0 = wm * 64 + i * 16 + grp;
                    if (m0 < mrows) {
                        float2 v = make_float2(acc[i][j][0] + bb.x, acc[i][j][1] + bb.y);
                        *(float2*)(Cout + (size_t)(row_start + m0) * Ncols + col) = v;
                    }
                    if (m0 + 8 < mrows) {
                        float2 v = make_float2(acc[i][j][2] + bb.x, acc[i][j][3] + bb.y);
                        *(float2*)(Cout + (size_t)(row_start + m0 + 8) * Ncols + col) = v;
                    }
                }
            }
        }
    }
}

// Zero any padding rows (tokens >= sum(ntpe)). No-op when the split sums to N.
__global__ void zero_tail_kernel(float* __restrict__ out, const int* __restrict__ ntpe,
                                 int E, int Ntok, int D) {
    int total = 0;
    for (int i = 0; i < E; i++) total += ntpe[i];
    if (total >= Ntok) return;
    size_t nelem  = (size_t)(Ntok - total) * D;
    float* base   = out + (size_t)total * D;
    size_t idx    = (size_t)blockIdx.x * blockDim.x + threadIdx.x;
    size_t stride = (size_t)gridDim.x * blockDim.x;
    for (; idx < nelem; idx += stride) base[idx] = 0.0f;
}

// ---------------------------------------------------------------------------

extern "C" void kernel_launch(void* const* d_in, const int* in_sizes, int n_in,
                              void* d_out, int out_size) {
    const float* x   = (const float*)d_in[0];
    const float* w1  = (const float*)d_in[1];
    const float* b1  = (const float*)d_in[2];
    const float* w2  = (const float*)d_in[3];
    const float* b2  = (const float*)d_in[4];
    const int*   ntp = (const int*)  d_in[5];

    int E  = in_sizes[5];                 // 8
    int D  = in_sizes[4] / E;             // 2880
    int H2 = in_sizes[2] / E;             // 5760
    int H  = H2 / 2;                      // 2880
    int N  = in_sizes[0] / D;             // 16384

    float* hptr = nullptr;
    cudaGetSymbolAddress((void**)&hptr, g_h);

    cudaFuncSetAttribute((const void*)grouped_gemm_tf32<0>,
                         cudaFuncAttributeMaxDynamicSharedMemorySize, SMEM_BYTES);
    cudaFuncSetAttribute((const void*)grouped_gemm_tf32<1>,
                         cudaFuncAttributeMaxDynamicSharedMemorySize, SMEM_BYTES);

    int mtiles_per_e = (N + BM - 1) / BM;             // 128

    // GEMM1 + bias + swiglu -> g_h [N, H]
    dim3 g1((H2 + BN - 1) / BN, E * mtiles_per_e);    // (45, 1024)
    grouped_gemm_tf32<0><<<g1, 256, SMEM_BYTES>>>(x, w1, b1, ntp, hptr,
                                                  /*K=*/D, /*Ncols=*/H2, E, mtiles_per_e, N);

    // GEMM2 + bias -> out [N, D]
    dim3 g2((D + BN - 1) / BN, E * mtiles_per_e);     // (23, 1024)
    grouped_gemm_tf32<1><<<g2, 256, SMEM_BYTES>>>(hptr, w2, b2, ntp, (float*)d_out,
                                                  /*K=*/H, /*Ncols=*/D, E, mtiles_per_e, N);

    // zero padding rows (no-op for the equal-split bench inputs)
    zero_tail_kernel<<<256, 256>>>((float*)d_out, ntp, E, N, D);
}